// round 4
// baseline (speedup 1.0000x reference)
#include <cuda_runtime.h>
#include <cstdint>
#include <cstddef>

#define BATCH   8
#define NPTS    8192
#define CDIM    6
#define NG      512
#define GS      32
#define FULLMASK 0xffffffffu

// output layout: neighborhood, center, idx (flattened tuple order, all f32)
#define NB_SZ  (BATCH * NG * GS * CDIM)   // 786432
#define C_OFF  (NB_SZ)
#define C_SZ   (BATCH * NG * 3)           // 12288
#define I_OFF  (C_OFF + C_SZ)             // 798720
#define I_SZ   (BATCH * NG * GS)          // 131072

// scratch (no allocations allowed -> __device__ globals)
__device__ float  g_xs[BATCH * NPTS];
__device__ float  g_ys[BATCH * NPTS];
__device__ float  g_zs[BATCH * NPTS];
__device__ float  g_pp[BATCH * NPTS];
__device__ float4 g_center[BATCH * NG];   // (cx, cy, cz, |c|^2)

// Sum of squares, ONE canonical rounding used at EVERY site:
//   t = x*x; t = fma(y,y,t); t = fma(z,z,t)
// (R1 evidence: FMA-contracted norms were closer to the reference than the
//  discrete mul/add tree; R1's residual single flip is attributed to
//  site-to-site contraction inconsistency, fixed here by explicit intrinsics.)
__device__ __forceinline__ float sumsq3(float x, float y, float z) {
    float t = __fmul_rn(x, x);
    t = __fmaf_rn(y, y, t);
    t = __fmaf_rn(z, z, t);
    return t;
}

__device__ __forceinline__ void argmax_red(float& v, int& vi) {
#pragma unroll
    for (int off = 16; off > 0; off >>= 1) {
        float ov = __shfl_down_sync(FULLMASK, v, off);
        int   oi = __shfl_down_sync(FULLMASK, vi, off);
        if (ov > v || (ov == v && oi < vi)) { v = ov; vi = oi; }
    }
}

// ---------------------------------------------------------------------------
// FPS: one CTA per batch. Points + running min-dist live in registers
// (8 pts/thread). SMEM mirror of points for broadcasting the chosen center.
// FPS *selection* arithmetic (dist update) is byte-identical to R1/R2:
// empirically all 4096 centers already match the reference.
// ---------------------------------------------------------------------------
__global__ void __launch_bounds__(1024, 1)
fps_kernel(const float* __restrict__ xyz, float* __restrict__ out, int out_size) {
    const int b   = blockIdx.x;
    const int tid = threadIdx.x;
    extern __shared__ float sh[];
    float* sx = sh;
    float* sy = sh + NPTS;
    float* sz = sh + 2 * NPTS;
    float* sv = sh + 3 * NPTS;        // 32 warp-partial values
    int*   si = (int*)(sv + 32);      // 32 warp-partial indices
    float* bq = (float*)(si + 32);    // broadcast of chosen center coords

    const float* base = xyz + (size_t)b * NPTS * CDIM;
    float px[8], py[8], pz[8], dist[8];
#pragma unroll
    for (int j = 0; j < 8; j++) {
        int i = j * 1024 + tid;
        float x = base[i * CDIM + 0];
        float y = base[i * CDIM + 1];
        float z = base[i * CDIM + 2];
        px[j] = x; py[j] = y; pz[j] = z;
        sx[i] = x; sy[i] = y; sz[i] = z;
        g_xs[b * NPTS + i] = x;
        g_ys[b * NPTS + i] = y;
        g_zs[b * NPTS + i] = z;
        g_pp[b * NPTS + i] = sumsq3(x, y, z);   // feeds kNN only, not FPS selection
        dist[j] = __int_as_float(0x7f800000);   // +inf: first update yields exact d(p, p0)
    }
    __syncthreads();

    float qx = sx[0], qy = sy[0], qz = sz[0];   // first FPS point is index 0
    if (tid == 0) {
        g_center[b * NG] = make_float4(qx, qy, qz, sumsq3(qx, qy, qz));
        if (out_size >= C_OFF + C_SZ) {
            out[C_OFF + (size_t)(b * NG) * 3 + 0] = qx;
            out[C_OFF + (size_t)(b * NG) * 3 + 1] = qy;
            out[C_OFF + (size_t)(b * NG) * 3 + 2] = qz;
        }
    }

    const int lane = tid & 31, wid = tid >> 5;
    for (int k = 1; k < NG; k++) {
        float v = -1.0f; int vi = 0;
#pragma unroll
        for (int j = 0; j < 8; j++) {
            float dx = px[j] - qx, dy = py[j] - qy, dz = pz[j] - qz;
            float d  = dx * dx + dy * dy + dz * dz;
            float nd = fminf(dist[j], d);
            dist[j] = nd;
            // strict > keeps earliest (lowest) index on ties; local scan order
            // j=0..7 visits strictly increasing point indices.
            if (nd > v) { v = nd; vi = j * 1024 + tid; }
        }
        argmax_red(v, vi);
        if (lane == 0) { sv[wid] = v; si[wid] = vi; }
        __syncthreads();
        if (wid == 0) {
            v = sv[lane]; vi = si[lane];
            argmax_red(v, vi);
            if (lane == 0) {
                int far = vi;
                float fx = sx[far], fy = sy[far], fz = sz[far];
                bq[0] = fx; bq[1] = fy; bq[2] = fz;
                g_center[b * NG + k] = make_float4(fx, fy, fz, sumsq3(fx, fy, fz));
                if (out_size >= C_OFF + C_SZ) {
                    out[C_OFF + (size_t)(b * NG + k) * 3 + 0] = fx;
                    out[C_OFF + (size_t)(b * NG + k) * 3 + 1] = fy;
                    out[C_OFF + (size_t)(b * NG + k) * 3 + 2] = fz;
                }
            }
        }
        __syncthreads();
        qx = bq[0]; qy = bq[1]; qz = bq[2];
    }
}

// ---------------------------------------------------------------------------
// kNN top-32 + gather: one warp per (b, g) group. Running top-32 kept sorted
// across lanes by key (d2, idx) ascending; lane 31 = current threshold.
// Distance rounding model (best fit to R1/R2 evidence):
//   dot  : FMUL; FFMA; FFMA          (== fma K-chain with acc0 = 0)
//   d2   : fsub(fadd(cc, pp), fmul(2, dot))
//          (equivalent under rounding to any fma(-2,dot,s) form: 2*dot exact)
// ---------------------------------------------------------------------------
__device__ __forceinline__ float ref_dist(float4 c, float x, float y, float z, float p2) {
    float dot = __fmul_rn(c.x, x);
    dot = __fmaf_rn(c.y, y, dot);
    dot = __fmaf_rn(c.z, z, dot);
    return __fsub_rn(__fadd_rn(c.w, p2), __fmul_rn(2.0f, dot));
}

__device__ __forceinline__ bool key_less(float ad, int ai, float bd, int bi) {
    return (ad < bd) || (ad == bd && ai < bi);   // JAX top_k tie rule: lower index wins
}

__global__ void __launch_bounds__(256, 8)
knn_kernel(const float* __restrict__ xyz, float* __restrict__ out, int out_size) {
    const int lane = threadIdx.x & 31;
    const int warp = (int)((blockIdx.x * blockDim.x + threadIdx.x) >> 5);
    const int b = warp >> 9;              // / NG
    const float4 c = g_center[warp];
    const float* xs = g_xs + b * NPTS;
    const float* ys = g_ys + b * NPTS;
    const float* zs = g_zs + b * NPTS;
    const float* pp = g_pp + b * NPTS;

    float Sd; int Si;
    {
        float x = xs[lane], y = ys[lane], z = zs[lane], p2 = pp[lane];
        Sd = ref_dist(c, x, y, z, p2);
        Si = lane;
    }
    // bitonic sort first 32 candidates ascending across lanes
#pragma unroll
    for (int k = 2; k <= 32; k <<= 1) {
        const bool dd = (lane & k) != 0;
#pragma unroll
        for (int j = k >> 1; j > 0; j >>= 1) {
            float od = __shfl_xor_sync(FULLMASK, Sd, j);
            int   oi = __shfl_xor_sync(FULLMASK, Si, j);
            bool lower = key_less(od, oi, Sd, Si);
            bool takeSmaller = (((lane & j) == 0) != dd);
            if (lower == takeSmaller) { Sd = od; Si = oi; }
        }
    }
    float Td = __shfl_sync(FULLMASK, Sd, 31);
    int   Ti = __shfl_sync(FULLMASK, Si, 31);

    for (int basei = 32; basei < NPTS; basei += 32) {
        int i = basei + lane;
        float x = xs[i], y = ys[i], z = zs[i], p2 = pp[i];
        float d = ref_dist(c, x, y, z, p2);
        unsigned m = __ballot_sync(FULLMASK, key_less(d, i, Td, Ti));
        while (m) {
            int src = __ffs(m) - 1; m &= m - 1;
            float cd = __shfl_sync(FULLMASK, d, src);
            int   ci = __shfl_sync(FULLMASK, i, src);
            if (key_less(cd, ci, Td, Ti)) {          // re-check vs updated threshold
                int pos = __popc(__ballot_sync(FULLMASK, key_less(Sd, Si, cd, ci)));
                float ud = __shfl_up_sync(FULLMASK, Sd, 1);
                int   ui = __shfl_up_sync(FULLMASK, Si, 1);
                if (lane == pos)      { Sd = cd; Si = ci; }
                else if (lane > pos)  { Sd = ud; Si = ui; }
                Td = __shfl_sync(FULLMASK, Sd, 31);
                Ti = __shfl_sync(FULLMASK, Si, 31);
            }
        }
    }

    // gather + write outputs (lane l holds the l-th nearest neighbor)
    const float* pb = xyz + (size_t)b * NPTS * CDIM;
    const int n = Si;
    float r0 = pb[n * CDIM + 0] - c.x;
    float r1 = pb[n * CDIM + 1] - c.y;
    float r2 = pb[n * CDIM + 2] - c.z;
    float e0 = pb[n * CDIM + 3];
    float e1 = pb[n * CDIM + 4];
    float e2 = pb[n * CDIM + 5];
    size_t o = ((size_t)warp * GS + lane) * CDIM;
    out[o + 0] = r0;
    out[o + 1] = r1;
    out[o + 2] = r2;
    out[o + 3] = e0;
    out[o + 4] = e1;
    out[o + 5] = e2;
    if (out_size >= I_OFF + I_SZ)
        out[I_OFF + (size_t)warp * GS + lane] = (float)n;
}

extern "C" void kernel_launch(void* const* d_in, const int* in_sizes, int n_in,
                              void* d_out, int out_size) {
    const float* xyz = (const float*)d_in[0];
    float* out = (float*)d_out;
    (void)in_sizes; (void)n_in;

    const size_t smem = (size_t)(3 * NPTS) * sizeof(float)
                      + 32 * sizeof(float) + 32 * sizeof(int) + 4 * sizeof(float);
    cudaFuncSetAttribute(fps_kernel, cudaFuncAttributeMaxDynamicSharedMemorySize, (int)smem);

    fps_kernel<<<BATCH, 1024, smem>>>(xyz, out, out_size);
    knn_kernel<<<(BATCH * NG * 32) / 256, 256>>>(xyz, out, out_size);
}

// round 5
// speedup vs baseline: 1.7480x; 1.7480x over previous
#include <cuda_runtime.h>
#include <cstdint>
#include <cstddef>

#define BATCH   8
#define NPTS    8192
#define CDIM    6
#define NG      512
#define GS      32
#define FULLMASK 0xffffffffu

// output layout: neighborhood, center, idx (flattened tuple order, all f32)
#define NB_SZ  (BATCH * NG * GS * CDIM)   // 786432
#define C_OFF  (NB_SZ)
#define C_SZ   (BATCH * NG * 3)           // 12288
#define I_OFF  (C_OFF + C_SZ)             // 798720
#define I_SZ   (BATCH * NG * GS)          // 131072

// scratch (no allocations allowed -> __device__ globals)
__device__ float4 g_pts[BATCH * NPTS];    // (x, y, z, |p|^2)
__device__ float4 g_center[BATCH * NG];   // (cx, cy, cz, |c|^2)

// ---------------------------------------------------------------------------
// packed f32x2 helpers (Blackwell FFMA2 path; per-component RN rounding is
// identical to the scalar FMUL/FFMA chain, so selection stays bit-exact)
// ---------------------------------------------------------------------------
__device__ __forceinline__ unsigned long long pk2(float lo, float hi) {
    unsigned long long r;
    asm("mov.b64 %0, {%1, %2};" : "=l"(r)
        : "r"(__float_as_uint(lo)), "r"(__float_as_uint(hi)));
    return r;
}
__device__ __forceinline__ void upk2(unsigned long long v, float& lo, float& hi) {
    unsigned a, b;
    asm("mov.b64 {%0, %1}, %2;" : "=r"(a), "=r"(b) : "l"(v));
    lo = __uint_as_float(a); hi = __uint_as_float(b);
}
__device__ __forceinline__ unsigned long long add2(unsigned long long a, unsigned long long b) {
    unsigned long long r;
    asm("add.rn.f32x2 %0, %1, %2;" : "=l"(r) : "l"(a), "l"(b));
    return r;
}
__device__ __forceinline__ unsigned long long mul2(unsigned long long a, unsigned long long b) {
    unsigned long long r;
    asm("mul.rn.f32x2 %0, %1, %2;" : "=l"(r) : "l"(a), "l"(b));
    return r;
}
__device__ __forceinline__ unsigned long long fma2(unsigned long long a, unsigned long long b,
                                                   unsigned long long c) {
    unsigned long long r;
    asm("fma.rn.f32x2 %0, %1, %2, %3;" : "=l"(r) : "l"(a), "l"(b), "l"(c));
    return r;
}

// Sum of squares, one canonical rounding at every site: t=x*x; fma(y,y,t); fma(z,z,t)
__device__ __forceinline__ float sumsq3(float x, float y, float z) {
    float t = __fmul_rn(x, x);
    t = __fmaf_rn(y, y, t);
    t = __fmaf_rn(z, z, t);
    return t;
}

// ---------------------------------------------------------------------------
// FPS: one CTA of 512 threads per batch, 16 pts/thread register-resident.
// Per step: packed-f32x2 distance update, redux-based argmax (tie -> lowest
// index), ONE __syncthreads (partials double-buffered by step parity), every
// warp redundantly reduces the 16 warp partials and reads the winner's coords
// from SMEM itself -- no second barrier, no broadcast roundtrip.
// Distance arithmetic is bit-identical to the R4-passing version.
// ---------------------------------------------------------------------------
#define FT  512
__global__ void __launch_bounds__(FT, 1)
fps_kernel(const float* __restrict__ xyz, float* __restrict__ out, int out_size) {
    const int b   = blockIdx.x;
    const int tid = threadIdx.x;
    extern __shared__ float sh[];
    float* sx = sh;
    float* sy = sh + NPTS;
    float* sz = sh + 2 * NPTS;
    unsigned* sv = (unsigned*)(sh + 3 * NPTS);   // [2][16] partial values
    unsigned* sidx = sv + 32;                    // [2][16] partial indices

    const float* base = xyz + (size_t)b * NPTS * CDIM;
    unsigned long long pxx[8], pyy[8], pzz[8];
    float dist[16];
    float prx = 0.f, pry = 0.f, prz = 0.f;
#pragma unroll
    for (int j = 0; j < 16; j++) {
        int i = j * FT + tid;
        float x = base[i * CDIM + 0];
        float y = base[i * CDIM + 1];
        float z = base[i * CDIM + 2];
        sx[i] = x; sy[i] = y; sz[i] = z;
        g_pts[b * NPTS + i] = make_float4(x, y, z, sumsq3(x, y, z));
        dist[j] = __int_as_float(0x7f800000);    // +inf
        if ((j & 1) == 0) { prx = x; pry = y; prz = z; }
        else {
            pxx[j >> 1] = pk2(prx, x);
            pyy[j >> 1] = pk2(pry, y);
            pzz[j >> 1] = pk2(prz, z);
        }
    }
    __syncthreads();

    float qx = sx[0], qy = sy[0], qz = sz[0];    // first FPS point is index 0
    if (tid == 0) {
        g_center[b * NG] = make_float4(qx, qy, qz, sumsq3(qx, qy, qz));
        if (out_size >= C_OFF + C_SZ) {
            out[C_OFF + (size_t)(b * NG) * 3 + 0] = qx;
            out[C_OFF + (size_t)(b * NG) * 3 + 1] = qy;
            out[C_OFF + (size_t)(b * NG) * 3 + 2] = qz;
        }
    }

    const int lane = tid & 31, wid = tid >> 5;
    for (int k = 1; k < NG; k++) {
        const unsigned long long nqx2 = pk2(-qx, -qx);
        const unsigned long long nqy2 = pk2(-qy, -qy);
        const unsigned long long nqz2 = pk2(-qz, -qz);
        float v = -1.0f; unsigned vi = 0;
#pragma unroll
        for (int j = 0; j < 8; j++) {
            // per component: dx = px + (-qx)  (== px - qx exactly)
            unsigned long long dx2 = add2(pxx[j], nqx2);
            unsigned long long dy2 = add2(pyy[j], nqy2);
            unsigned long long dz2 = add2(pzz[j], nqz2);
            unsigned long long t  = mul2(dx2, dx2);
            t = fma2(dy2, dy2, t);
            t = fma2(dz2, dz2, t);
            float dlo, dhi; upk2(t, dlo, dhi);
            float nd = fminf(dist[2 * j], dlo);
            dist[2 * j] = nd;
            if (nd > v) { v = nd; vi = (unsigned)((2 * j) * FT + tid); }
            nd = fminf(dist[2 * j + 1], dhi);
            dist[2 * j + 1] = nd;
            if (nd > v) { v = nd; vi = (unsigned)((2 * j + 1) * FT + tid); }
        }
        // level-1: warp argmax, tie -> lowest index (v >= 0 so bits are monotone)
        unsigned vb = __float_as_uint(v);
        unsigned M  = __reduce_max_sync(FULLMASK, vb);
        unsigned cand = (vb == M) ? vi : 0xffffffffu;
        unsigned mi = __reduce_min_sync(FULLMASK, cand);
        const int slot = (k & 1) << 4;
        if (lane == 0) { sv[slot + wid] = M; sidx[slot + wid] = mi; }
        __syncthreads();
        // level-2: every warp redundantly reduces the 16 partials
        int l = slot + (lane & 15);
        unsigned pv = sv[l], pi = sidx[l];
        unsigned M2 = __reduce_max_sync(FULLMASK, pv);
        unsigned cand2 = (pv == M2) ? pi : 0xffffffffu;
        unsigned far = __reduce_min_sync(FULLMASK, cand2);
        qx = sx[far]; qy = sy[far]; qz = sz[far];
        if (tid == 0) {
            g_center[b * NG + k] = make_float4(qx, qy, qz, sumsq3(qx, qy, qz));
            if (out_size >= C_OFF + C_SZ) {
                out[C_OFF + (size_t)(b * NG + k) * 3 + 0] = qx;
                out[C_OFF + (size_t)(b * NG + k) * 3 + 1] = qy;
                out[C_OFF + (size_t)(b * NG + k) * 3 + 2] = qz;
            }
        }
    }
}

// ---------------------------------------------------------------------------
// kNN top-32 + gather: one warp per (b, g) group. Running top-32 kept sorted
// across lanes by key (d2, idx) ascending; lane 31 = current threshold.
// Distance chain (bit-exact to the passing R4 version):
//   dot: FMUL; FFMA; FFMA   d2: fsub(fadd(cc, pp), fmul(2, dot))
// ---------------------------------------------------------------------------
__device__ __forceinline__ float ref_dist(float4 c, float x, float y, float z, float p2) {
    float dot = __fmul_rn(c.x, x);
    dot = __fmaf_rn(c.y, y, dot);
    dot = __fmaf_rn(c.z, z, dot);
    return __fsub_rn(__fadd_rn(c.w, p2), __fmul_rn(2.0f, dot));
}

__device__ __forceinline__ bool key_less(float ad, int ai, float bd, int bi) {
    return (ad < bd) || (ad == bd && ai < bi);   // JAX top_k tie rule: lower index wins
}

__global__ void __launch_bounds__(256, 8)
knn_kernel(const float* __restrict__ xyz, float* __restrict__ out, int out_size) {
    const int lane = threadIdx.x & 31;
    const int warp = (int)((blockIdx.x * blockDim.x + threadIdx.x) >> 5);
    const int b = warp >> 9;              // / NG
    const float4 c = g_center[warp];
    const float4* pts = g_pts + b * NPTS;

    float Sd; int Si;
    {
        float4 p = pts[lane];
        Sd = ref_dist(c, p.x, p.y, p.z, p.w);
        Si = lane;
    }
    // bitonic sort first 32 candidates ascending across lanes
#pragma unroll
    for (int k = 2; k <= 32; k <<= 1) {
        const bool dd = (lane & k) != 0;
#pragma unroll
        for (int j = k >> 1; j > 0; j >>= 1) {
            float od = __shfl_xor_sync(FULLMASK, Sd, j);
            int   oi = __shfl_xor_sync(FULLMASK, Si, j);
            bool lower = key_less(od, oi, Sd, Si);
            bool takeSmaller = (((lane & j) == 0) != dd);
            if (lower == takeSmaller) { Sd = od; Si = oi; }
        }
    }
    float Td = __shfl_sync(FULLMASK, Sd, 31);
    int   Ti = __shfl_sync(FULLMASK, Si, 31);

    float4 p = pts[32 + lane];
    for (int basei = 32; basei < NPTS; basei += 32) {
        float4 pn = p;
        if (basei + 32 < NPTS) pn = pts[basei + 32 + lane];   // software pipeline
        const int i = basei + lane;
        float d = ref_dist(c, p.x, p.y, p.z, p.w);
        unsigned m = __ballot_sync(FULLMASK, key_less(d, i, Td, Ti));
        if (m) {
            do {
                int src = __ffs(m) - 1; m &= m - 1;
                float cd = __shfl_sync(FULLMASK, d, src);
                int   ci = basei + src;                 // index is arithmetic, no shfl
                // NOTE: no re-check vs updated threshold. A stale-qualifying
                // candidate worse than all 32 gets pos=32 -> provable no-op.
                int pos = __popc(__ballot_sync(FULLMASK, key_less(Sd, Si, cd, ci)));
                float ud = __shfl_up_sync(FULLMASK, Sd, 1);
                int   ui = __shfl_up_sync(FULLMASK, Si, 1);
                if (lane == pos)      { Sd = cd; Si = ci; }
                else if (lane > pos)  { Sd = ud; Si = ui; }
            } while (m);
            Td = __shfl_sync(FULLMASK, Sd, 31);         // refresh once per batch
            Ti = __shfl_sync(FULLMASK, Si, 31);
        }
        p = pn;
    }

    // gather + write outputs (lane l holds the l-th nearest neighbor)
    const int n = Si;
    float4 pw = pts[n];                                  // exact copies of xyz[:3]
    const float* pb = xyz + ((size_t)b * NPTS + n) * CDIM;
    float e0 = pb[3], e1 = pb[4], e2 = pb[5];
    float2 w0 = make_float2(pw.x - c.x, pw.y - c.y);
    float2 w1 = make_float2(pw.z - c.z, e0);
    float2 w2 = make_float2(e1, e2);
    float2* ob = (float2*)out + ((size_t)warp * GS + lane) * 3;
    ob[0] = w0; ob[1] = w1; ob[2] = w2;
    if (out_size >= I_OFF + I_SZ)
        out[I_OFF + (size_t)warp * GS + lane] = (float)n;
}

extern "C" void kernel_launch(void* const* d_in, const int* in_sizes, int n_in,
                              void* d_out, int out_size) {
    const float* xyz = (const float*)d_in[0];
    float* out = (float*)d_out;
    (void)in_sizes; (void)n_in;

    const size_t smem = (size_t)(3 * NPTS) * sizeof(float) + 64 * sizeof(unsigned);
    cudaFuncSetAttribute(fps_kernel, cudaFuncAttributeMaxDynamicSharedMemorySize, (int)smem);

    fps_kernel<<<BATCH, FT, smem>>>(xyz, out, out_size);
    knn_kernel<<<(BATCH * NG * 32) / 256, 256>>>(xyz, out, out_size);
}